// round 13
// baseline (speedup 1.0000x reference)
#include <cuda_runtime.h>
#include <cuda_fp16.h>
#include <cstdint>

// Shapes fixed by the problem: M=1024, K=4096, N=4096, group size 128.
#define M_DIM 1024
#define K_DIM 4096
#define N_DIM 4096

// Scratch (__device__ global; cudaMalloc forbidden): x converted fp32 -> fp16.
__device__ __half g_X[(size_t)M_DIM * K_DIM];

// ===========================================================================
// helpers
// ===========================================================================
__device__ __forceinline__ uint32_t smem_u32(const void* p) {
    uint32_t a;
    asm("{ .reg .u64 t; cvta.to.shared.u64 t, %1; cvt.u32.u64 %0, t; }"
        : "=r"(a) : "l"(p));
    return a;
}
__device__ __forceinline__ void cp16(uint32_t dst, const __half* src) {
    size_t g = __cvta_generic_to_global((const void*)src);
    asm volatile("cp.async.cg.shared.global [%0], [%1], 16;\n" :: "r"(dst), "l"(g));
}
__device__ __forceinline__ void ldm_x4(uint32_t* r, uint32_t addr) {
    asm volatile("ldmatrix.sync.aligned.m8n8.x4.shared.b16 {%0,%1,%2,%3}, [%4];"
                 : "=r"(r[0]), "=r"(r[1]), "=r"(r[2]), "=r"(r[3]) : "r"(addr));
}
__device__ __forceinline__ void mma16816(float* d, const uint32_t* a,
                                         uint32_t b0, uint32_t b1) {
    asm volatile("mma.sync.aligned.m16n8k16.row.col.f32.f16.f16.f32 "
                 "{%0,%1,%2,%3}, {%4,%5,%6,%7}, {%8,%9}, {%0,%1,%2,%3};"
                 : "+f"(d[0]), "+f"(d[1]), "+f"(d[2]), "+f"(d[3])
                 : "r"(a[0]), "r"(a[1]), "r"(a[2]), "r"(a[3]), "r"(b0), "r"(b1));
}

// ===========================================================================
// Kernel 0: x fp32 -> fp16 (lossless; harness upcasts fp16 inputs to fp32).
// ===========================================================================
__global__ void convert_x_kernel(const float* __restrict__ x, size_t n) {
    size_t i = ((size_t)blockIdx.x * blockDim.x + threadIdx.x) * 8;
    if (i >= n) return;
    float4 a = *(const float4*)&x[i];
    float4 b = *(const float4*)&x[i + 4];
    __half2 h0 = __floats2half2_rn(a.x, a.y);
    __half2 h1 = __floats2half2_rn(a.z, a.w);
    __half2 h2 = __floats2half2_rn(b.x, b.y);
    __half2 h3 = __floats2half2_rn(b.z, b.w);
    uint4 u;
    u.x = *(uint32_t*)&h0; u.y = *(uint32_t*)&h1;
    u.z = *(uint32_t*)&h2; u.w = *(uint32_t*)&h3;
    *(uint4*)&g_X[i] = u;
}

// ===========================================================================
// Kernel 1: fused GPTQ-dequant + GEMM + bias.
//   out[M][N] = x @ W + bias,  W[k][n] = (q - (z+1)) * scale[g][n]
// CTA 128M x 256N, BK=64, 3-stage ring, 512 threads (16 warps, 2m x 8n),
// warp tile 64x32. B stored [n][k] K-major 128B rows (XOR-swizzled); dequant
// via fp16 magic-number trick (no I2F): h=(v|0x6400)==1024+v; w=(h-(1025+z))*s.
// ===========================================================================
#define BM 128
#define BN 256
#define BKC 64
#define STAGES 3
#define ASTG (BM * BKC * 2)        // 16 KB
#define BSTG (BN * BKC * 2)        // 32 KB
#define STG  (ASTG + BSTG)         // 48 KB
#define SMEM_TOT (STAGES * STG)    // 144 KB

__global__ __launch_bounds__(512, 1)
void gemm_fused_kernel(const int* __restrict__ qw,
                       const float* __restrict__ scales,
                       const int* __restrict__ qz,
                       const int* __restrict__ gidx,
                       const float* __restrict__ bias,
                       float* __restrict__ out,
                       int M, int N, int K) {
    extern __shared__ char sm[];
    const int tid  = threadIdx.x;
    const int lane = tid & 31;
    const int warp = tid >> 5;
    const int wm   = (warp & 1) * 64;     // 2 warps along M
    const int wn   = (warp >> 1) * 32;    // 8 warps along N
    const int mb   = blockIdx.y * BM;
    const int nb   = blockIdx.x * BN;
    const uint32_t sbase = smem_u32(sm);

    float acc[4][4][4];
#pragma unroll
    for (int i = 0; i < 4; i++)
#pragma unroll
        for (int j = 0; j < 4; j++)
#pragma unroll
            for (int c = 0; c < 4; c++) acc[i][j][c] = 0.0f;

    const int NKC = K / BKC;              // 64
    // dequant ownership: thread t -> column n = nb + (t&255), k-half = t>>8
    const int ncol  = tid & 255;
    const int khalf = tid >> 8;           // 0 or 1 (words 0-3 / 4-7 of chunk)
    const int n_g   = nb + ncol;

    // ---- fetch qweight words + scale/zero for one k-chunk into regs ----
    uint32_t wq[4];
    __half2  s2, off2;
    auto fetchB = [&](int kc) {
        int k0 = kc * BKC;
        int g  = gidx[k0];                // GS=128 >= BKC: uniform per chunk
        float sf = scales[(size_t)g * N + n_g];
        unsigned zw = (unsigned)qz[(size_t)g * (N >> 3) + (n_g >> 3)];
        int z = (int)((zw >> ((n_g & 7) * 4)) & 15u);
        s2   = __half2half2(__float2half(sf));
        off2 = __half2half2(__float2half((float)(1025 + z)));
        int kp0 = (k0 >> 3) + khalf * 4;
#pragma unroll
        for (int j = 0; j < 4; j++)
            wq[j] = (uint32_t)qw[(size_t)(kp0 + j) * N + n_g];
    };

    // ---- dequant regs -> B stage buffer ([n][k], chunk-XOR swizzle) ----
    auto stsB = [&](int st) {
        char* rowp = sm + st * STG + ASTG + (size_t)ncol * 128;
        const int r7 = ncol & 7;
#pragma unroll
        for (int j = 0; j < 4; j++) {
            uint32_t q = wq[j];
            int kp = khalf * 4 + j;
            uint4 u;
#pragma unroll
            for (int p = 0; p < 4; p++) {         // pairs (v2p, v2p+1)
                uint32_t lo = (q >> (8 * p))     & 0xFu;
                uint32_t hi = (q >> (8 * p + 4)) & 0xFu;
                uint32_t hb = lo | (hi << 16) | 0x64006400u;
                __half2 hv = *(__half2*)&hb;
                __half2 w  = __hmul2(__hsub2(hv, off2), s2);
                ((uint32_t*)&u)[p] = *(uint32_t*)&w;
            }
            *(uint4*)(rowp + ((kp ^ r7) * 16)) = u;
        }
    };

    // ---- A stage loader: 128 rows x 128B via cp.async ----
    auto cpA = [&](int st, int kc) {
        int k0 = kc * BKC;
        uint32_t sa = sbase + st * STG;
#pragma unroll
        for (int t = 0; t < 2; t++) {
            int idx = t * 512 + tid;
            int r = idx >> 3, c = idx & 7;
            cp16(sa + r * 128 + ((c ^ (r & 7)) * 16),
                 g_X + (size_t)(mb + r) * K + k0 + c * 8);
        }
    };

    // ---- prologue: stages 0 and 1 ----
    fetchB(0); stsB(0); cpA(0, 0);
    asm volatile("cp.async.commit_group;\n" ::: "memory");
    fetchB(1); stsB(1); cpA(1, 1);
    asm volatile("cp.async.commit_group;\n" ::: "memory");
    asm volatile("cp.async.wait_group 1;\n" ::: "memory");
    __syncthreads();                      // stage 0 resident

    // ---- mainloop ----
    for (int kc = 0; kc < NKC; kc++) {
        const int cur = kc % 3;
        if (kc + 2 < NKC) fetchB(kc + 2);     // LDG latency hides under MMAs

        const uint32_t sa = sbase + cur * STG;
        const uint32_t sb = sa + ASTG;
#pragma unroll
        for (int kk = 0; kk < 4; kk++) {
            uint32_t a[4][4];
#pragma unroll
            for (int mi = 0; mi < 4; mi++) {
                int row = wm + mi * 16 + (lane & 15);
                int c   = kk * 2 + (lane >> 4);
                ldm_x4(a[mi], sa + row * 128 + ((c ^ (row & 7)) * 16));
            }
#pragma unroll
            for (int ni = 0; ni < 2; ni++) {
                uint32_t b[4];
                int row = wn + ni * 16 + ((lane >> 4) * 8) + (lane & 7);
                int c   = kk * 2 + ((lane >> 3) & 1);
                ldm_x4(b, sb + row * 128 + ((c ^ (row & 7)) * 16));
#pragma unroll
                for (int mi = 0; mi < 4; mi++) {
                    mma16816(acc[mi][2 * ni],     a[mi], b[0], b[1]);
                    mma16816(acc[mi][2 * ni + 1], a[mi], b[2], b[3]);
                }
            }
        }

        if (kc + 2 < NKC) {
            int st = (kc + 2) % 3;        // == (kc-1)%3: freed by last barrier
            stsB(st);
            cpA(st, kc + 2);
        }
        asm volatile("cp.async.commit_group;\n" ::: "memory");
        asm volatile("cp.async.wait_group 1;\n" ::: "memory");  // stage kc+1 A done
        __syncthreads();
    }

    // ---- epilogue: + bias, fp32 out ----
    const int gq = lane >> 2, tq = lane & 3;
#pragma unroll
    for (int mi = 0; mi < 4; mi++) {
        int row0 = mb + wm + mi * 16 + gq;
#pragma unroll
        for (int ng = 0; ng < 4; ng++) {
            int col = nb + wn + ng * 8 + tq * 2;
            float b0 = bias[col];
            float b1 = bias[col + 1];
            float2 v0 = make_float2(acc[mi][ng][0] + b0, acc[mi][ng][1] + b1);
            float2 v1 = make_float2(acc[mi][ng][2] + b0, acc[mi][ng][3] + b1);
            *(float2*)&out[(size_t)row0 * N + col]       = v0;
            *(float2*)&out[(size_t)(row0 + 8) * N + col] = v1;
        }
    }
}

// ===========================================================================
// Launch: inputs in metadata order: x, qweight, scales, qzeros, g_idx, bias
// (fp16 tensors arrive upcast to float32)
// ===========================================================================
extern "C" void kernel_launch(void* const* d_in, const int* in_sizes, int n_in,
                              void* d_out, int out_size) {
    const float* x       = (const float*)d_in[0];
    const int*   qweight = (const int*)d_in[1];
    const float* scales  = (const float*)d_in[2];
    const int*   qzeros  = (const int*)d_in[3];
    const int*   g_idx   = (const int*)d_in[4];
    const float* bias    = (const float*)d_in[5];
    float*       out     = (float*)d_out;

    const int K = in_sizes[4];          // g_idx length
    const int N = in_sizes[5];          // bias length
    const int M = in_sizes[0] / K;      // x is [M, K]

    // 0) x fp32 -> fp16
    size_t nx = (size_t)M * K;
    convert_x_kernel<<<(unsigned)((nx / 8 + 255) / 256), 256>>>(x, nx);

    // 1) fused dequant + GEMM + bias (16 x 8 = 128 CTAs, one wave)
    static bool attr_set = false;
    if (!attr_set) {
        cudaFuncSetAttribute(gemm_fused_kernel,
                             cudaFuncAttributeMaxDynamicSharedMemorySize, SMEM_TOT);
        attr_set = true;
    }
    dim3 gg(N / BN, M / BM);
    gemm_fused_kernel<<<gg, 512, SMEM_TOT>>>(qweight, scales, qzeros, g_idx,
                                             bias, out, M, N, K);
}

// round 14
// speedup vs baseline: 1.1890x; 1.1890x over previous
#include <cuda_runtime.h>
#include <cuda_fp16.h>
#include <cstdint>

// Shapes fixed by the problem: M=1024, K=4096, N=4096, group size 128.
#define M_DIM 1024
#define K_DIM 4096
#define N_DIM 4096

// Scratch (__device__ global; cudaMalloc forbidden): x converted fp32 -> fp16.
__device__ __half g_X[(size_t)M_DIM * K_DIM];

// ===========================================================================
// helpers
// ===========================================================================
__device__ __forceinline__ uint32_t smem_u32(const void* p) {
    uint32_t a;
    asm("{ .reg .u64 t; cvta.to.shared.u64 t, %1; cvt.u32.u64 %0, t; }"
        : "=r"(a) : "l"(p));
    return a;
}
__device__ __forceinline__ void cp16(uint32_t dst, const __half* src) {
    size_t g = __cvta_generic_to_global((const void*)src);
    asm volatile("cp.async.cg.shared.global [%0], [%1], 16;\n" :: "r"(dst), "l"(g));
}
__device__ __forceinline__ void ldm_x4(uint32_t* r, uint32_t addr) {
    asm volatile("ldmatrix.sync.aligned.m8n8.x4.shared.b16 {%0,%1,%2,%3}, [%4];"
                 : "=r"(r[0]), "=r"(r[1]), "=r"(r[2]), "=r"(r[3]) : "r"(addr));
}
__device__ __forceinline__ void mma16816(float* d, const uint32_t* a,
                                         uint32_t b0, uint32_t b1) {
    asm volatile("mma.sync.aligned.m16n8k16.row.col.f32.f16.f16.f32 "
                 "{%0,%1,%2,%3}, {%4,%5,%6,%7}, {%8,%9}, {%0,%1,%2,%3};"
                 : "+f"(d[0]), "+f"(d[1]), "+f"(d[2]), "+f"(d[3])
                 : "r"(a[0]), "r"(a[1]), "r"(a[2]), "r"(a[3]), "r"(b0), "r"(b1));
}

#define MBAR_INIT(addr, cnt) \
    asm volatile("mbarrier.init.shared.b64 [%0], %1;" :: "r"(addr), "r"(cnt) : "memory")
#define MBAR_ARRIVE(addr) \
    asm volatile("mbarrier.arrive.shared.b64 _, [%0];" :: "r"(addr) : "memory")
#define CPASYNC_MBAR_ARRIVE_NOINC(addr) \
    asm volatile("cp.async.mbarrier.arrive.noinc.shared.b64 [%0];" :: "r"(addr) : "memory")
#define MBAR_WAIT(addr, parity) do {                                              \
    uint32_t _m = (addr); uint32_t _p = (parity); uint32_t _d;                    \
    asm volatile("{\n\t.reg .pred p;\n\t"                                         \
        "mbarrier.try_wait.parity.shared.b64 p, [%1], %2;\n\t"                    \
        "selp.b32 %0, 1, 0, p;\n\t}"                                              \
        : "=r"(_d) : "r"(_m), "r"(_p) : "memory");                                \
    if (!_d) {                                                                    \
        asm volatile("{\n\t.reg .pred P1;\n\t"                                    \
            "WL_%=:\n\t"                                                          \
            "mbarrier.try_wait.parity.shared.b64 P1, [%0], %1;\n\t"               \
            "@P1 bra.uni WD_%=;\n\t"                                              \
            "bra.uni WL_%=;\n\t"                                                  \
            "WD_%=:\n\t}"                                                         \
            :: "r"(_m), "r"(_p) : "memory");                                      \
    }                                                                             \
} while (0)

// ===========================================================================
// Kernel 0: x fp32 -> fp16 (lossless; harness upcasts fp16 inputs to fp32).
// ===========================================================================
__global__ void convert_x_kernel(const float* __restrict__ x, size_t n) {
    size_t i = ((size_t)blockIdx.x * blockDim.x + threadIdx.x) * 8;
    if (i >= n) return;
    float4 a = *(const float4*)&x[i];
    float4 b = *(const float4*)&x[i + 4];
    __half2 h0 = __floats2half2_rn(a.x, a.y);
    __half2 h1 = __floats2half2_rn(a.z, a.w);
    __half2 h2 = __floats2half2_rn(b.x, b.y);
    __half2 h3 = __floats2half2_rn(b.z, b.w);
    uint4 u;
    u.x = *(uint32_t*)&h0; u.y = *(uint32_t*)&h1;
    u.z = *(uint32_t*)&h2; u.w = *(uint32_t*)&h3;
    *(uint4*)&g_X[i] = u;
}

// ===========================================================================
// Kernel 1: warp-specialized fused GPTQ-dequant + GEMM + bias.
//   640 threads: warps 0-15 consumers (ldmatrix+mma only, 64x32 warp tiles),
//   warps 16-19 producers (qweight LDG -> magic dequant -> STS B; cp.async A).
//   3-stage SMEM ring, mbarrier full/empty handshake, no __syncthreads in loop.
// ===========================================================================
#define BM 128
#define BN 256
#define BKC 64
#define STAGES 3
#define ASTG (BM * BKC * 2)        // 16 KB
#define BSTG (BN * BKC * 2)        // 32 KB
#define STG  (ASTG + BSTG)         // 48 KB
#define SMEM_TOT (STAGES * STG)    // 144 KB
#define NCONS 512                   // consumer threads

__global__ __launch_bounds__(640, 1)
void gemm_fused_kernel(const int* __restrict__ qw,
                       const float* __restrict__ scales,
                       const int* __restrict__ qz,
                       const int* __restrict__ gidx,
                       const float* __restrict__ bias,
                       float* __restrict__ out,
                       int M, int N, int K) {
    extern __shared__ char sm[];
    __shared__ __align__(8) unsigned long long full_s[STAGES], empty_s[STAGES];

    const int tid  = threadIdx.x;
    const int lane = tid & 31;
    const int warp = tid >> 5;
    const int mb   = blockIdx.y * BM;
    const int nb   = blockIdx.x * BN;
    const uint32_t sbase = smem_u32(sm);
    uint32_t fullb[STAGES], emptyb[STAGES];
#pragma unroll
    for (int s = 0; s < STAGES; s++) {
        fullb[s]  = smem_u32(&full_s[s]);
        emptyb[s] = smem_u32(&empty_s[s]);
    }

    if (tid == 0) {
#pragma unroll
        for (int s = 0; s < STAGES; s++) {
            MBAR_INIT(fullb[s], 256);   // 128 STS arrives + 128 cp.async arrives
            MBAR_INIT(emptyb[s], NCONS);
        }
    }
    __syncthreads();

    const int NKC = K / BKC;            // 64

    if (warp >= 16) {
        // =================== PRODUCER (128 threads) =====================
        const int tp = tid - NCONS;     // 0..127
        const int n0 = nb + tp * 2;     // two adjacent weight columns

        uint32_t wqb[2][16];            // [buf][col*8 + kp]
        __half2  s2b[2][2], of2b[2][2];

        auto fetchB = [&](int kc, int buf) {
            int g = gidx[kc * BKC];     // GS=128 >= BKC: uniform per chunk
            float2 sf = *(const float2*)&scales[(size_t)g * N + n0];
            unsigned zw = (unsigned)qz[(size_t)g * (N >> 3) + (n0 >> 3)];
            int z0 = (int)((zw >> ((n0 & 7) * 4)) & 15u);
            int z1 = (int)((zw >> (((n0 & 7) + 1) * 4)) & 15u);
            s2b[buf][0]  = __half2half2(__float2half(sf.x));
            s2b[buf][1]  = __half2half2(__float2half(sf.y));
            of2b[buf][0] = __half2half2(__float2half((float)(1025 + z0)));
            of2b[buf][1] = __half2half2(__float2half((float)(1025 + z1)));
            int kp0 = kc * (BKC / 8);
#pragma unroll
            for (int j = 0; j < 8; j++) {
                int2 w = *(const int2*)&qw[(size_t)(kp0 + j) * N + n0];
                wqb[buf][j]     = (uint32_t)w.x;
                wqb[buf][8 + j] = (uint32_t)w.y;
            }
        };

        auto stsB = [&](int st, int buf) {
#pragma unroll
            for (int c = 0; c < 2; c++) {
                int ncol = tp * 2 + c;
                char* rowp = sm + st * STG + ASTG + (size_t)ncol * 128;
                int r7 = ncol & 7;
                __half2 s2 = s2b[buf][c], of2 = of2b[buf][c];
#pragma unroll
                for (int kp = 0; kp < 8; kp++) {
                    uint32_t q = wqb[buf][c * 8 + kp];
                    uint4 u;
#pragma unroll
                    for (int p = 0; p < 4; p++) {
                        uint32_t lo = (q >> (8 * p))     & 0xFu;
                        uint32_t hi = (q >> (8 * p + 4)) & 0xFu;
                        uint32_t hb = lo | (hi << 16) | 0x64006400u;
                        __half2 hv = *(__half2*)&hb;
                        __half2 w  = __hmul2(__hsub2(hv, of2), s2);
                        ((uint32_t*)&u)[p] = *(uint32_t*)&w;
                    }
                    *(uint4*)(rowp + ((kp ^ r7) * 16)) = u;
                }
            }
        };

        auto cpA = [&](int st, int kc) {
            int k0 = kc * BKC;
            uint32_t sa = sbase + st * STG;
#pragma unroll
            for (int t = 0; t < 8; t++) {
                int idx = t * 128 + tp;
                int r = idx >> 3, c = idx & 7;
                cp16(sa + r * 128 + ((c ^ (r & 7)) * 16),
                     g_X + (size_t)(mb + r) * K + k0 + c * 8);
            }
        };

        fetchB(0, 0);
        int st = 0, ph = 1;             // producer starts phase 1: empty passes
        for (int kc = 0; kc < NKC; kc++) {
            if (kc + 1 < NKC) fetchB(kc + 1, (kc + 1) & 1);
            MBAR_WAIT(emptyb[st], ph);
            stsB(st, kc & 1);
            cpA(st, kc);
            CPASYNC_MBAR_ARRIVE_NOINC(fullb[st]);   // arrives when cp.asyncs land
            MBAR_ARRIVE(fullb[st]);                  // releases the STS writes
            if (++st == STAGES) { st = 0; ph ^= 1; }
        }
        return;
    }

    // ===================== CONSUMER (512 threads) =======================
    const int wm = (warp & 1) * 64;     // 2 warps along M
    const int wn = (warp >> 1) * 32;    // 8 warps along N

    float acc[4][4][4];
#pragma unroll
    for (int i = 0; i < 4; i++)
#pragma unroll
        for (int j = 0; j < 4; j++)
#pragma unroll
            for (int c = 0; c < 4; c++) acc[i][j][c] = 0.0f;

    int st = 0, ph = 0;
    for (int kc = 0; kc < NKC; kc++) {
        MBAR_WAIT(fullb[st], ph);
        const uint32_t sa = sbase + st * STG;
        const uint32_t sb = sa + ASTG;
#pragma unroll
        for (int kk = 0; kk < 4; kk++) {
            uint32_t a[4][4];
#pragma unroll
            for (int mi = 0; mi < 4; mi++) {
                int row = wm + mi * 16 + (lane & 15);
                int c   = kk * 2 + (lane >> 4);
                ldm_x4(a[mi], sa + row * 128 + ((c ^ (row & 7)) * 16));
            }
#pragma unroll
            for (int ni = 0; ni < 2; ni++) {
                uint32_t b[4];
                int row = wn + ni * 16 + ((lane >> 4) * 8) + (lane & 7);
                int c   = kk * 2 + ((lane >> 3) & 1);
                ldm_x4(b, sb + row * 128 + ((c ^ (row & 7)) * 16));
#pragma unroll
                for (int mi = 0; mi < 4; mi++) {
                    mma16816(acc[mi][2 * ni],     a[mi], b[0], b[1]);
                    mma16816(acc[mi][2 * ni + 1], a[mi], b[2], b[3]);
                }
            }
        }
        MBAR_ARRIVE(emptyb[st]);
        if (++st == STAGES) { st = 0; ph ^= 1; }
    }

    // ---- epilogue: + bias, fp32 out ----
    const int gq = lane >> 2, tq = lane & 3;
#pragma unroll
    for (int mi = 0; mi < 4; mi++) {
        int row0 = mb + wm + mi * 16 + gq;
#pragma unroll
        for (int ng = 0; ng < 4; ng++) {
            int col = nb + wn + ng * 8 + tq * 2;
            float b0 = bias[col];
            float b1 = bias[col + 1];
            float2 v0 = make_float2(acc[mi][ng][0] + b0, acc[mi][ng][1] + b1);
            float2 v1 = make_float2(acc[mi][ng][2] + b0, acc[mi][ng][3] + b1);
            *(float2*)&out[(size_t)row0 * N + col]       = v0;
            *(float2*)&out[(size_t)(row0 + 8) * N + col] = v1;
        }
    }
}

// ===========================================================================
// Launch: inputs in metadata order: x, qweight, scales, qzeros, g_idx, bias
// (fp16 tensors arrive upcast to float32)
// ===========================================================================
extern "C" void kernel_launch(void* const* d_in, const int* in_sizes, int n_in,
                              void* d_out, int out_size) {
    const float* x       = (const float*)d_in[0];
    const int*   qweight = (const int*)d_in[1];
    const float* scales  = (const float*)d_in[2];
    const int*   qzeros  = (const int*)d_in[3];
    const int*   g_idx   = (const int*)d_in[4];
    const float* bias    = (const float*)d_in[5];
    float*       out     = (float*)d_out;

    const int K = in_sizes[4];          // g_idx length
    const int N = in_sizes[5];          // bias length
    const int M = in_sizes[0] / K;      // x is [M, K]

    // 0) x fp32 -> fp16
    size_t nx = (size_t)M * K;
    convert_x_kernel<<<(unsigned)((nx / 8 + 255) / 256), 256>>>(x, nx);

    // 1) warp-specialized fused dequant + GEMM + bias (128 CTAs, one wave)
    static bool attr_set = false;
    if (!attr_set) {
        cudaFuncSetAttribute(gemm_fused_kernel,
                             cudaFuncAttributeMaxDynamicSharedMemorySize, SMEM_TOT);
        attr_set = true;
    }
    dim3 gg(N / BN, M / BM);
    gemm_fused_kernel<<<gg, 640, SMEM_TOT>>>(qweight, scales, qzeros, g_idx,
                                             bias, out, M, N, K);
}

// round 15
// speedup vs baseline: 1.1980x; 1.0076x over previous
#include <cuda_runtime.h>
#include <cuda_fp16.h>
#include <cstdint>

// Shapes fixed by the problem: M=1024, K=4096, N=4096, group size 128.
#define M_DIM 1024
#define K_DIM 4096
#define N_DIM 4096

// Scratch (__device__ global; cudaMalloc forbidden): x converted fp32 -> fp16.
__device__ __half g_X[(size_t)M_DIM * K_DIM];

// ===========================================================================
// helpers
// ===========================================================================
__device__ __forceinline__ uint32_t smem_u32(const void* p) {
    uint32_t a;
    asm("{ .reg .u64 t; cvta.to.shared.u64 t, %1; cvt.u32.u64 %0, t; }"
        : "=r"(a) : "l"(p));
    return a;
}
__device__ __forceinline__ void cp16(uint32_t dst, const __half* src) {
    size_t g = __cvta_generic_to_global((const void*)src);
    asm volatile("cp.async.cg.shared.global [%0], [%1], 16;\n" :: "r"(dst), "l"(g));
}
__device__ __forceinline__ void ldm_x4(uint32_t* r, uint32_t addr) {
    asm volatile("ldmatrix.sync.aligned.m8n8.x4.shared.b16 {%0,%1,%2,%3}, [%4];"
                 : "=r"(r[0]), "=r"(r[1]), "=r"(r[2]), "=r"(r[3]) : "r"(addr));
}
__device__ __forceinline__ void mma16816(float* d, const uint32_t* a,
                                         uint32_t b0, uint32_t b1) {
    asm volatile("mma.sync.aligned.m16n8k16.row.col.f32.f16.f16.f32 "
                 "{%0,%1,%2,%3}, {%4,%5,%6,%7}, {%8,%9}, {%0,%1,%2,%3};"
                 : "+f"(d[0]), "+f"(d[1]), "+f"(d[2]), "+f"(d[3])
                 : "r"(a[0]), "r"(a[1]), "r"(a[2]), "r"(a[3]), "r"(b0), "r"(b1));
}

#define MBAR_INIT(addr, cnt) \
    asm volatile("mbarrier.init.shared.b64 [%0], %1;" :: "r"(addr), "r"(cnt) : "memory")
#define MBAR_ARRIVE(addr) \
    asm volatile("mbarrier.arrive.shared.b64 _, [%0];" :: "r"(addr) : "memory")
#define CPASYNC_MBAR_ARRIVE_NOINC(addr) \
    asm volatile("cp.async.mbarrier.arrive.noinc.shared.b64 [%0];" :: "r"(addr) : "memory")
#define MBAR_WAIT(addr, parity) do {                                              \
    uint32_t _m = (addr); uint32_t _p = (parity); uint32_t _d;                    \
    asm volatile("{\n\t.reg .pred p;\n\t"                                         \
        "mbarrier.try_wait.parity.shared.b64 p, [%1], %2;\n\t"                    \
        "selp.b32 %0, 1, 0, p;\n\t}"                                              \
        : "=r"(_d) : "r"(_m), "r"(_p) : "memory");                                \
    if (!_d) {                                                                    \
        asm volatile("{\n\t.reg .pred P1;\n\t"                                    \
            "WL_%=:\n\t"                                                          \
            "mbarrier.try_wait.parity.shared.b64 P1, [%0], %1;\n\t"               \
            "@P1 bra.uni WD_%=;\n\t"                                              \
            "bra.uni WL_%=;\n\t"                                                  \
            "WD_%=:\n\t}"                                                         \
            :: "r"(_m), "r"(_p) : "memory");                                      \
    }                                                                             \
} while (0)

// ===========================================================================
// Kernel 0: x fp32 -> fp16 (lossless; harness upcasts fp16 inputs to fp32).
// ===========================================================================
__global__ void convert_x_kernel(const float* __restrict__ x, size_t n) {
    size_t i = ((size_t)blockIdx.x * blockDim.x + threadIdx.x) * 8;
    if (i >= n) return;
    float4 a = *(const float4*)&x[i];
    float4 b = *(const float4*)&x[i + 4];
    __half2 h0 = __floats2half2_rn(a.x, a.y);
    __half2 h1 = __floats2half2_rn(a.z, a.w);
    __half2 h2 = __floats2half2_rn(b.x, b.y);
    __half2 h3 = __floats2half2_rn(b.z, b.w);
    uint4 u;
    u.x = *(uint32_t*)&h0; u.y = *(uint32_t*)&h1;
    u.z = *(uint32_t*)&h2; u.w = *(uint32_t*)&h3;
    *(uint4*)&g_X[i] = u;
}

// ===========================================================================
// Kernel 1: warp-specialized fused GPTQ-dequant + GEMM + bias.
//   384 threads: warps 0-7 consumers (pure ldmatrix+mma, 64x64 warp tiles —
//   minimal LDS-bytes/FLOP), warps 8-11 producers (qweight LDG -> magic
//   dequant -> STS B; cp.async A). 4-stage ring, mbarrier handshake,
//   no __syncthreads in the mainloop.
// ===========================================================================
#define BM 128
#define BN 256
#define BKC 64
#define STAGES 4
#define ASTG (BM * BKC * 2)        // 16 KB
#define BSTG (BN * BKC * 2)        // 32 KB
#define STG  (ASTG + BSTG)         // 48 KB
#define SMEM_TOT (STAGES * STG)    // 192 KB
#define NCONS 256                   // consumer threads (8 warps)

__global__ __launch_bounds__(384, 1)
void gemm_fused_kernel(const int* __restrict__ qw,
                       const float* __restrict__ scales,
                       const int* __restrict__ qz,
                       const int* __restrict__ gidx,
                       const float* __restrict__ bias,
                       float* __restrict__ out,
                       int M, int N, int K) {
    extern __shared__ char sm[];
    __shared__ __align__(8) unsigned long long full_s[STAGES], empty_s[STAGES];

    const int tid  = threadIdx.x;
    const int lane = tid & 31;
    const int warp = tid >> 5;
    const int mb   = blockIdx.y * BM;
    const int nb   = blockIdx.x * BN;
    const uint32_t sbase = smem_u32(sm);
    uint32_t fullb[STAGES], emptyb[STAGES];
#pragma unroll
    for (int s = 0; s < STAGES; s++) {
        fullb[s]  = smem_u32(&full_s[s]);
        emptyb[s] = smem_u32(&empty_s[s]);
    }

    if (tid == 0) {
#pragma unroll
        for (int s = 0; s < STAGES; s++) {
            MBAR_INIT(fullb[s], 256);   // 128 STS arrives + 128 cp.async arrives
            MBAR_INIT(emptyb[s], NCONS);
        }
    }
    __syncthreads();

    const int NKC = K / BKC;            // 64

    if (warp >= 8) {
        // =================== PRODUCER (128 threads) =====================
        const int tp = tid - NCONS;     // 0..127
        const int n0 = nb + tp * 2;     // two adjacent weight columns

        uint32_t wqb[2][16];            // [buf][col*8 + kp]
        __half2  s2b[2][2], of2b[2][2];

        auto fetchB = [&](int kc, int buf) {
            int g = gidx[kc * BKC];     // GS=128 >= BKC: uniform per chunk
            float2 sf = *(const float2*)&scales[(size_t)g * N + n0];
            unsigned zw = (unsigned)qz[(size_t)g * (N >> 3) + (n0 >> 3)];
            int z0 = (int)((zw >> ((n0 & 7) * 4)) & 15u);
            int z1 = (int)((zw >> (((n0 & 7) + 1) * 4)) & 15u);
            s2b[buf][0]  = __half2half2(__float2half(sf.x));
            s2b[buf][1]  = __half2half2(__float2half(sf.y));
            of2b[buf][0] = __half2half2(__float2half((float)(1025 + z0)));
            of2b[buf][1] = __half2half2(__float2half((float)(1025 + z1)));
            int kp0 = kc * (BKC / 8);
#pragma unroll
            for (int j = 0; j < 8; j++) {
                int2 w = *(const int2*)&qw[(size_t)(kp0 + j) * N + n0];
                wqb[buf][j]     = (uint32_t)w.x;
                wqb[buf][8 + j] = (uint32_t)w.y;
            }
        };

        auto stsB = [&](int st, int buf) {
#pragma unroll
            for (int c = 0; c < 2; c++) {
                int ncol = tp * 2 + c;
                char* rowp = sm + st * STG + ASTG + (size_t)ncol * 128;
                int r7 = ncol & 7;
                __half2 s2 = s2b[buf][c], of2 = of2b[buf][c];
#pragma unroll
                for (int kp = 0; kp < 8; kp++) {
                    uint32_t q = wqb[buf][c * 8 + kp];
                    uint4 u;
#pragma unroll
                    for (int p = 0; p < 4; p++) {
                        uint32_t lo = (q >> (8 * p))     & 0xFu;
                        uint32_t hi = (q >> (8 * p + 4)) & 0xFu;
                        uint32_t hb = lo | (hi << 16) | 0x64006400u;
                        __half2 hv = *(__half2*)&hb;
                        __half2 w  = __hmul2(__hsub2(hv, of2), s2);
                        ((uint32_t*)&u)[p] = *(uint32_t*)&w;
                    }
                    *(uint4*)(rowp + ((kp ^ r7) * 16)) = u;
                }
            }
        };

        auto cpA = [&](int st, int kc) {
            int k0 = kc * BKC;
            uint32_t sa = sbase + st * STG;
#pragma unroll
            for (int t = 0; t < 8; t++) {
                int idx = t * 128 + tp;
                int r = idx >> 3, c = idx & 7;
                cp16(sa + r * 128 + ((c ^ (r & 7)) * 16),
                     g_X + (size_t)(mb + r) * K + k0 + c * 8);
            }
        };

        fetchB(0, 0);
        int st = 0, ph = 1;             // producer starts phase 1: empty passes
        for (int kc = 0; kc < NKC; kc++) {
            if (kc + 1 < NKC) fetchB(kc + 1, (kc + 1) & 1);
            MBAR_WAIT(emptyb[st], ph);
            cpA(st, kc);                // copies in flight during dequant ALU
            stsB(st, kc & 1);
            CPASYNC_MBAR_ARRIVE_NOINC(fullb[st]);   // arrives when cp.asyncs land
            MBAR_ARRIVE(fullb[st]);                  // releases the STS writes
            if (++st == STAGES) { st = 0; ph ^= 1; }
        }
        return;
    }

    // ===================== CONSUMER (256 threads) =======================
    const int wm = (warp & 1) * 64;     // 2 warps along M
    const int wn = (warp >> 1) * 64;    // 4 warps along N

    float acc[4][8][4];
#pragma unroll
    for (int i = 0; i < 4; i++)
#pragma unroll
        for (int j = 0; j < 8; j++)
#pragma unroll
            for (int c = 0; c < 4; c++) acc[i][j][c] = 0.0f;

    int st = 0, ph = 0;
    for (int kc = 0; kc < NKC; kc++) {
        MBAR_WAIT(fullb[st], ph);
        const uint32_t sa = sbase + st * STG;
        const uint32_t sb = sa + ASTG;
#pragma unroll
        for (int kk = 0; kk < 4; kk++) {
            uint32_t a[4][4];
#pragma unroll
            for (int mi = 0; mi < 4; mi++) {
                int row = wm + mi * 16 + (lane & 15);
                int c   = kk * 2 + (lane >> 4);
                ldm_x4(a[mi], sa + row * 128 + ((c ^ (row & 7)) * 16));
            }
#pragma unroll
            for (int ni = 0; ni < 4; ni++) {
                uint32_t b[4];
                int row = wn + ni * 16 + ((lane >> 4) * 8) + (lane & 7);
                int c   = kk * 2 + ((lane >> 3) & 1);
                ldm_x4(b, sb + row * 128 + ((c ^ (row & 7)) * 16));
#pragma unroll
                for (int mi = 0; mi < 4; mi++) {
                    mma16816(acc[mi][2 * ni],     a[mi], b[0], b[1]);
                    mma16816(acc[mi][2 * ni + 1], a[mi], b[2], b[3]);
                }
            }
        }
        MBAR_ARRIVE(emptyb[st]);
        if (++st == STAGES) { st = 0; ph ^= 1; }
    }

    // ---- epilogue: + bias, fp32 out ----
    const int gq = lane >> 2, tq = lane & 3;
#pragma unroll
    for (int mi = 0; mi < 4; mi++) {
        int row0 = mb + wm + mi * 16 + gq;
#pragma unroll
        for (int ng = 0; ng < 8; ng++) {
            int col = nb + wn + ng * 8 + tq * 2;
            float b0 = bias[col];
            float b1 = bias[col + 1];
            float2 v0 = make_float2(acc[mi][ng][0] + b0, acc[mi][ng][1] + b1);
            float2 v1 = make_float2(acc[mi][ng][2] + b0, acc[mi][ng][3] + b1);
            *(float2*)&out[(size_t)row0 * N + col]       = v0;
            *(float2*)&out[(size_t)(row0 + 8) * N + col] = v1;
        }
    }
}

// ===========================================================================
// Launch: inputs in metadata order: x, qweight, scales, qzeros, g_idx, bias
// (fp16 tensors arrive upcast to float32)
// ===========================================================================
extern "C" void kernel_launch(void* const* d_in, const int* in_sizes, int n_in,
                              void* d_out, int out_size) {
    const float* x       = (const float*)d_in[0];
    const int*   qweight = (const int*)d_in[1];
    const float* scales  = (const float*)d_in[2];
    const int*   qzeros  = (const int*)d_in[3];
    const int*   g_idx   = (const int*)d_in[4];
    const float* bias    = (const float*)d_in[5];
    float*       out     = (float*)d_out;

    const int K = in_sizes[4];          // g_idx length
    const int N = in_sizes[5];          // bias length
    const int M = in_sizes[0] / K;      // x is [M, K]

    // 0) x fp32 -> fp16
    size_t nx = (size_t)M * K;
    convert_x_kernel<<<(unsigned)((nx / 8 + 255) / 256), 256>>>(x, nx);

    // 1) warp-specialized fused dequant + GEMM + bias (128 CTAs, one wave)
    static bool attr_set = false;
    if (!attr_set) {
        cudaFuncSetAttribute(gemm_fused_kernel,
                             cudaFuncAttributeMaxDynamicSharedMemorySize, SMEM_TOT);
        attr_set = true;
    }
    dim3 gg(N / BN, M / BM);
    gemm_fused_kernel<<<gg, 384, SMEM_TOT>>>(qweight, scales, qzeros, g_idx,
                                             bias, out, M, N, K);
}